// round 13
// baseline (speedup 1.0000x reference)
#include <cuda_runtime.h>
#include <cuda_fp16.h>
#include <cstdint>

#define B 512
#define DX 128
#define H 512

// ---------------- scratch (no allocs allowed) ----------------
__device__ float g_hx[B * H];
__device__ float g_hyb[B * H];
__device__ __half g_W2h[H * H];

// ---------------------------------------------------------------------------
// Layer 1: out[r][h] = sum_d in[r][d] * W1[h][off+d] (+ b1[h] if addb)
// ---------------------------------------------------------------------------
__global__ void gemm_h_kernel(const float* __restrict__ in,
                              const float* __restrict__ W1,
                              const float* __restrict__ b1,
                              int off, int addb) {
    __shared__ float xs[16][17];
    __shared__ float ws[16][17];
    int tx = threadIdx.x, ty = threadIdx.y;
    int r0 = blockIdx.y * 16, h0 = blockIdx.x * 16;
    float acc = 0.f;
    for (int kt = 0; kt < DX; kt += 16) {
        xs[ty][tx] = in[(r0 + ty) * DX + kt + tx];
        ws[ty][tx] = W1[(h0 + ty) * (2 * DX) + off + kt + tx];
        __syncthreads();
#pragma unroll
        for (int k = 0; k < 16; k++)
            acc = fmaf(xs[ty][k], ws[tx][k], acc);
        __syncthreads();
    }
    float bv = addb ? b1[h0 + tx] : 0.f;
    float* outp = addb ? g_hyb : g_hx;
    outp[(r0 + ty) * H + h0 + tx] = acc + bv;
}

// ---------------------------------------------------------------------------
// Convert W2 fp32 -> fp16 (single copy)
// ---------------------------------------------------------------------------
__global__ void wconv_kernel(const float* __restrict__ W2) {
    int idx = blockIdx.x * 256 + threadIdx.x;
    g_W2h[idx] = __float2half_rn(W2[idx]);
}

// ---------------------------------------------------------------------------
// helpers
// ---------------------------------------------------------------------------
__device__ __forceinline__ uint32_t smem_u32(const void* p) {
    uint32_t a;
    asm("{ .reg .u64 t; cvta.to.shared.u64 t, %1; cvt.u32.u64 %0, t; }"
        : "=r"(a) : "l"(p));
    return a;
}
__device__ __forceinline__ void ldm_x4(uint32_t& r0, uint32_t& r1,
                                       uint32_t& r2, uint32_t& r3, uint32_t a) {
    asm volatile("ldmatrix.sync.aligned.m8n8.x4.shared.b16 {%0,%1,%2,%3}, [%4];"
                 : "=r"(r0), "=r"(r1), "=r"(r2), "=r"(r3) : "r"(a));
}
__device__ __forceinline__ void mma16816(float* c, uint32_t a0, uint32_t a1,
                                         uint32_t a2, uint32_t a3,
                                         uint32_t b0, uint32_t b1) {
    asm volatile(
        "mma.sync.aligned.m16n8k16.row.col.f32.f16.f16.f32 "
        "{%0,%1,%2,%3}, {%4,%5,%6,%7}, {%8,%9}, {%0,%1,%2,%3};"
        : "+f"(c[0]), "+f"(c[1]), "+f"(c[2]), "+f"(c[3])
        : "r"(a0), "r"(a1), "r"(a2), "r"(a3), "r"(b0), "r"(b1));
}
__device__ __forceinline__ void cp16(uint32_t dst, const void* src) {
    asm volatile("cp.async.cg.shared.global [%0], [%1], 16;"
                 :: "r"(dst), "l"(src));
}
__device__ __forceinline__ void mbar_init(uint32_t a, uint32_t cnt) {
    asm volatile("mbarrier.init.shared.b64 [%0], %1;" :: "r"(a), "r"(cnt)
                 : "memory");
}
__device__ __forceinline__ void mbar_arrive(uint32_t a) {
    asm volatile("mbarrier.arrive.shared.b64 _, [%0];" :: "r"(a) : "memory");
}
// .noinc is load-bearing: without it the arrive INCREMENTS the expected count
// (self-balancing) and a 512-count barrier never completes (R8 hang).
__device__ __forceinline__ void cp_async_mbar_arrive(uint32_t a) {
    asm volatile("cp.async.mbarrier.arrive.noinc.shared.b64 [%0];" :: "r"(a)
                 : "memory");
}
__device__ __forceinline__ void mbar_wait(uint32_t a, uint32_t parity) {
    asm volatile(
        "{\n\t.reg .pred P;\n\t"
        "WL_%=:\n\t"
        "mbarrier.try_wait.parity.shared.b64 P, [%0], %1, 0x989680;\n\t"
        "@P bra.uni WD_%=;\n\t"
        "bra.uni WL_%=;\n\t"
        "WD_%=:\n\t}"
        :: "r"(a), "r"(parity) : "memory");
}

// ---------------------------------------------------------------------------
// Main fused kernel: fp16 HMMA, mbarrier free-running pipeline, 384B/MMA,
// and per-warp k-phase rotation to break SMSP phase-locking.
//
// KEY CHANGE vs R12: warps on one SMSP share w&3 (=mw) but differ in nw.
// Rotating the k16-step order by nw (kse = (ks+nw)&3) puts the 4 warps of
// each SMSP in different LDSM/MMA phases, so the LSU bursts of one warp
// overlap the tensor bursts of its siblings instead of phase-locking
// (R5-R12 invariant: tensor pinned ~51% with L1 also unsaturated).
// Accumulation order over k only changes rounding.
// ---------------------------------------------------------------------------
#define SM_A    0          // 8 chunks x [128 rows x 128B] = 128KB
#define SM_W    131072     // 2 bufs x 32KB = 64KB
#define SM_BW   196608     // float2[512] = 4KB
#define SM_RED  200704     // float[4][128] = 2KB
#define SM_MBAR 202752     // full[2], empty[2] = 32B
#define SMEM_TOTAL 202816

__global__ __launch_bounds__(512, 1)
void critic_hmma(const float* __restrict__ b2,
                 const float* __restrict__ W3,
                 const float* __restrict__ b3p,
                 float* __restrict__ out) {
    extern __shared__ char smem[];
    const uint32_t sb = smem_u32(smem);
    const int t = threadIdx.x;
    const int lane = t & 31;
    const int w = t >> 5;
    const int mw = w & 3;        // m-warp: 0..3 (32 rows each) == SMSP id
    const int nw = w >> 2;       // n-warp: 0..3 (64 cols each within stage)
    const int g = lane >> 2;
    const int t4 = lane & 3;
    const int i0 = blockIdx.y * 8;
    const int j0 = blockIdx.x * 16;

    const uint32_t FULL = sb + SM_MBAR;         // full[b] = FULL + b*8
    const uint32_t EMPTY = sb + SM_MBAR + 16;   // empty[b] = EMPTY + b*8

    if (t == 0) {
#pragma unroll
        for (int b = 0; b < 2; b++) {
            mbar_init(FULL + b * 8, 512);
            mbar_init(EMPTY + b * 8, 512);
        }
    }

    for (int q = t; q < 512; q += 512)
        *(float2*)(smem + SM_BW + q * 8) = make_float2(b2[q], W3[q]);

    // ---- prologue: generate full A [128m x 512k] fp16 into smem (once)
    {
#pragma unroll 4
        for (int r = 0; r < 16; ++r) {
            int item = t + r * 512;
            int kc = item >> 10;
            int row = (item >> 3) & 127;
            int c = item & 7;
            int kg = kc * 64 + c * 8;
            const float* hxp = &g_hx[(i0 + (row >> 4)) * H + kg];
            const float* hyp = &g_hyb[(j0 + (row & 15)) * H + kg];
            float4 x0 = *(const float4*)hxp, x1 = *(const float4*)(hxp + 4);
            float4 y0 = *(const float4*)hyp, y1 = *(const float4*)(hyp + 4);
            __half2 h0 = __float22half2_rn(make_float2(
                fmaxf(x0.x + y0.x, 0.f), fmaxf(x0.y + y0.y, 0.f)));
            __half2 h1 = __float22half2_rn(make_float2(
                fmaxf(x0.z + y0.z, 0.f), fmaxf(x0.w + y0.w, 0.f)));
            __half2 h2 = __float22half2_rn(make_float2(
                fmaxf(x1.x + y1.x, 0.f), fmaxf(x1.y + y1.y, 0.f)));
            __half2 h3 = __float22half2_rn(make_float2(
                fmaxf(x1.z + y1.z, 0.f), fmaxf(x1.w + y1.w, 0.f)));
            uint32_t off = (uint32_t)(kc * 16384 + row * 128) +
                           (((uint32_t)(c * 16)) ^ ((uint32_t)((row & 7) << 4)));
            *(uint4*)(smem + SM_A + off) =
                make_uint4(*(uint32_t*)&h0, *(uint32_t*)&h1,
                           *(uint32_t*)&h2, *(uint32_t*)&h3);
        }
    }
    __syncthreads();   // covers mbar init + A tile + BW preload

    // W producer: stage sp -> nt = sp>>3, kc = sp&7, buf = sp&1
    auto produceW = [&](int sp) {
        const int nt = sp >> 3, kc = sp & 7, buf = sp & 1;
#pragma unroll
        for (int r = 0; r < 4; ++r) {
            int item = t + r * 512;
            int n = item >> 3;          // 0..255 (local n within stage)
            int c = item & 7;
            const __half* src = &g_W2h[(nt * 256 + n) * H + kc * 64 + c * 8];
            uint32_t off = (uint32_t)(buf * 32768 + n * 128) +
                           (((uint32_t)(c * 16)) ^ ((uint32_t)((n & 7) << 4)));
            cp16(sb + SM_W + off, src);
        }
        cp_async_mbar_arrive(FULL + buf * 8);
    };

    // ldmatrix A lane mapping (warp covers rows mw*32 .. +32)
    const int a_row_l = lane & 15;
    const int a_kh = lane >> 4;
    uint32_t a_base[2], a_cs[2];
#pragma unroll
    for (int tm = 0; tm < 2; tm++) {
        int row = mw * 32 + tm * 16 + a_row_l;
        a_base[tm] = sb + SM_A + row * 128;
        a_cs[tm] = (uint32_t)((row & 7) << 4) ^ (uint32_t)(a_kh * 16);
    }
    // ldmatrix B lane mapping (x4 covers 16 n x 16 k); p = 0..3 -> 64 local n
    const int b_n_l = ((lane >> 4) << 3) + (lane & 7);
    const int b_kh = (lane >> 3) & 1;
    uint32_t b_off[4], b_cs[4];
#pragma unroll
    for (int p = 0; p < 4; p++) {
        int n = nw * 64 + p * 16 + b_n_l;   // local n within 256-n stage
        b_off[p] = (uint32_t)(n * 128);
        b_cs[p] = (uint32_t)((n & 7) << 4) ^ (uint32_t)(b_kh * 16);
    }

    float pm[4];
#pragma unroll
    for (int q = 0; q < 4; q++) pm[q] = 0.f;

    float acc[2][8][4];
#pragma unroll
    for (int a = 0; a < 2; a++)
#pragma unroll
        for (int b = 0; b < 8; b++)
#pragma unroll
            for (int c = 0; c < 4; c++) acc[a][b][c] = 0.f;

    // prologue: fill both ring slots
    produceW(0);
    produceW(1);

    for (int s = 0; s < 16; ++s) {
        const int nt = s >> 3, kc = s & 7, buf = s & 1;

        mbar_wait(FULL + buf * 8, (uint32_t)((s >> 1) & 1));

        const uint32_t akc = (uint32_t)(kc * 16384);
        const uint32_t wbase = sb + SM_W + (uint32_t)(buf * 32768);
#pragma unroll
        for (int ks = 0; ks < 4; ks++) {
            // per-warp k-phase rotation: siblings on an SMSP (same mw,
            // different nw) work on different k16 steps at any instant.
            const int kse = (ks + nw) & 3;
            uint32_t af[2][4];
#pragma unroll
            for (int tm = 0; tm < 2; tm++)
                ldm_x4(af[tm][0], af[tm][1], af[tm][2], af[tm][3],
                       a_base[tm] + akc + ((uint32_t)(kse * 32) ^ a_cs[tm]));
            uint32_t bf[4][4];
#pragma unroll
            for (int p = 0; p < 4; p++)
                ldm_x4(bf[p][0], bf[p][1], bf[p][2], bf[p][3],
                       wbase + b_off[p] + ((uint32_t)(kse * 32) ^ b_cs[p]));
#pragma unroll
            for (int tm = 0; tm < 2; tm++)
#pragma unroll
                for (int tn = 0; tn < 8; tn++)
                    mma16816(acc[tm][tn], af[tm][0], af[tm][1], af[tm][2],
                             af[tm][3], bf[tn >> 1][(tn & 1) * 2],
                             bf[tn >> 1][(tn & 1) * 2 + 1]);
        }

        if (kc == 7) {
            // ---- fold this 256-n half: relu(D + b2) . W3 into pm
#pragma unroll
            for (int tm = 0; tm < 2; tm++)
#pragma unroll
                for (int tn = 0; tn < 8; tn++) {
                    int n_g = nt * 256 + nw * 64 + tn * 8 + 2 * t4;
                    float2 bw0 = *(const float2*)(smem + SM_BW + n_g * 8);
                    float2 bw1 = *(const float2*)(smem + SM_BW + (n_g + 1) * 8);
                    pm[tm * 2] = fmaf(fmaxf(acc[tm][tn][0] + bw0.x, 0.f), bw0.y,
                                      pm[tm * 2]);
                    pm[tm * 2] = fmaf(fmaxf(acc[tm][tn][1] + bw1.x, 0.f), bw1.y,
                                      pm[tm * 2]);
                    pm[tm * 2 + 1] = fmaf(fmaxf(acc[tm][tn][2] + bw0.x, 0.f),
                                          bw0.y, pm[tm * 2 + 1]);
                    pm[tm * 2 + 1] = fmaf(fmaxf(acc[tm][tn][3] + bw1.x, 0.f),
                                          bw1.y, pm[tm * 2 + 1]);
                    acc[tm][tn][0] = 0.f;
                    acc[tm][tn][1] = 0.f;
                    acc[tm][tn][2] = 0.f;
                    acc[tm][tn][3] = 0.f;
                }
        }

        // this warp is done reading buf
        mbar_arrive(EMPTY + buf * 8);

        // produce stage s+2 (ring-2)
        const int sp = s + 2;
        if (sp < 16) {
            mbar_wait(EMPTY + (sp & 1) * 8, (uint32_t)(((sp >> 1) - 1) & 1));
            produceW(sp);
        }
    }

    // ---- reduce pm across the 4 lanes of each row group
#pragma unroll
    for (int q = 0; q < 4; q++) {
        pm[q] += __shfl_xor_sync(0xffffffffu, pm[q], 1);
        pm[q] += __shfl_xor_sync(0xffffffffu, pm[q], 2);
    }
    __syncthreads();
    if (t4 == 0) {
        float* red = (float*)(smem + SM_RED);
#pragma unroll
        for (int tm = 0; tm < 2; tm++) {
            red[nw * 128 + mw * 32 + tm * 16 + g] = pm[tm * 2];
            red[nw * 128 + mw * 32 + tm * 16 + 8 + g] = pm[tm * 2 + 1];
        }
    }
    __syncthreads();
    if (t < 128) {
        const float* red = (const float*)(smem + SM_RED);
        float s = red[t] + red[128 + t] + red[256 + t] + red[384 + t] + b3p[0];
        out[(i0 + (t >> 4)) * B + j0 + (t & 15)] = s;
    }
}

// ---------------------------------------------------------------------------
extern "C" void kernel_launch(void* const* d_in, const int* in_sizes, int n_in,
                              void* d_out, int out_size) {
    const float* x  = (const float*)d_in[0];
    const float* y  = (const float*)d_in[1];
    const float* W1 = (const float*)d_in[2];
    const float* b1 = (const float*)d_in[3];
    const float* W2 = (const float*)d_in[4];
    const float* b2 = (const float*)d_in[5];
    const float* W3 = (const float*)d_in[6];
    const float* b3 = (const float*)d_in[7];
    float* out = (float*)d_out;

    cudaFuncSetAttribute(critic_hmma, cudaFuncAttributeMaxDynamicSharedMemorySize,
                         SMEM_TOTAL);

    dim3 gblk(16, 16);
    dim3 ggrd(H / 16, B / 16);
    gemm_h_kernel<<<ggrd, gblk>>>(x, W1, b1, 0, 0);    // -> g_hx
    gemm_h_kernel<<<ggrd, gblk>>>(y, W1, b1, DX, 1);   // -> g_hyb (+b1)
    wconv_kernel<<<H * H / 256, 256>>>(W2);            // -> g_W2h

    critic_hmma<<<dim3(B / 16, B / 8), 512, SMEM_TOTAL>>>(b2, W3, b3, out);
}

// round 14
// speedup vs baseline: 1.1733x; 1.1733x over previous
#include <cuda_runtime.h>
#include <cuda_fp16.h>
#include <cstdint>

#define B 512
#define DX 128
#define H 512

// ---------------- scratch (no allocs allowed) ----------------
__device__ float g_hx[B * H];
__device__ float g_hyb[B * H];
__device__ __half g_W2h[H * H];

// ---------------------------------------------------------------------------
// Layer 1: out[r][h] = sum_d in[r][d] * W1[h][off+d] (+ b1[h] if addb)
// ---------------------------------------------------------------------------
__global__ void gemm_h_kernel(const float* __restrict__ in,
                              const float* __restrict__ W1,
                              const float* __restrict__ b1,
                              int off, int addb) {
    __shared__ float xs[16][17];
    __shared__ float ws[16][17];
    int tx = threadIdx.x, ty = threadIdx.y;
    int r0 = blockIdx.y * 16, h0 = blockIdx.x * 16;
    float acc = 0.f;
    for (int kt = 0; kt < DX; kt += 16) {
        xs[ty][tx] = in[(r0 + ty) * DX + kt + tx];
        ws[ty][tx] = W1[(h0 + ty) * (2 * DX) + off + kt + tx];
        __syncthreads();
#pragma unroll
        for (int k = 0; k < 16; k++)
            acc = fmaf(xs[ty][k], ws[tx][k], acc);
        __syncthreads();
    }
    float bv = addb ? b1[h0 + tx] : 0.f;
    float* outp = addb ? g_hyb : g_hx;
    outp[(r0 + ty) * H + h0 + tx] = acc + bv;
}

// ---------------------------------------------------------------------------
// Convert W2 fp32 -> fp16 (single copy)
// ---------------------------------------------------------------------------
__global__ void wconv_kernel(const float* __restrict__ W2) {
    int idx = blockIdx.x * 256 + threadIdx.x;
    g_W2h[idx] = __float2half_rn(W2[idx]);
}

// ---------------------------------------------------------------------------
// helpers
// ---------------------------------------------------------------------------
__device__ __forceinline__ uint32_t smem_u32(const void* p) {
    uint32_t a;
    asm("{ .reg .u64 t; cvta.to.shared.u64 t, %1; cvt.u32.u64 %0, t; }"
        : "=r"(a) : "l"(p));
    return a;
}
__device__ __forceinline__ void ldm_x4(uint32_t& r0, uint32_t& r1,
                                       uint32_t& r2, uint32_t& r3, uint32_t a) {
    asm volatile("ldmatrix.sync.aligned.m8n8.x4.shared.b16 {%0,%1,%2,%3}, [%4];"
                 : "=r"(r0), "=r"(r1), "=r"(r2), "=r"(r3) : "r"(a));
}
__device__ __forceinline__ void mma16816(float* c, uint32_t a0, uint32_t a1,
                                         uint32_t a2, uint32_t a3,
                                         uint32_t b0, uint32_t b1) {
    asm volatile(
        "mma.sync.aligned.m16n8k16.row.col.f32.f16.f16.f32 "
        "{%0,%1,%2,%3}, {%4,%5,%6,%7}, {%8,%9}, {%0,%1,%2,%3};"
        : "+f"(c[0]), "+f"(c[1]), "+f"(c[2]), "+f"(c[3])
        : "r"(a0), "r"(a1), "r"(a2), "r"(a3), "r"(b0), "r"(b1));
}
__device__ __forceinline__ void cp16(uint32_t dst, const void* src) {
    asm volatile("cp.async.cg.shared.global [%0], [%1], 16;"
                 :: "r"(dst), "l"(src));
}

// ---------------------------------------------------------------------------
// Main fused kernel: fp16 HMMA, 2 CTAs/SM (the untried axis).
//
// R5-R13 invariant: tensor pinned ~51% with ONE CTA/SM regardless of tiling,
// sync scheme, or reg pipelining — every block-wide event stalls the whole
// SM. Fix: halve the CTA (m-tile 64 = 8i x 8j, 256 thr = 8 warps 2mw x 4nw,
// warp tile 32m x 64n kept for the 192B/MMA smem ratio) and drop full-A
// residency (A chunk regenerated per K-stage into an 8KB ring-2). smem ~85KB
// -> 2 independent CTAs co-resident: one CTA's barriers/stage boundaries are
// filled by the sibling's MMA stream.
// Stages: nt 0..1 (256-n halves) x kc 0..7 (64-k chunks) = 16.
// ---------------------------------------------------------------------------
#define SM_A    0          // 2 bufs x [64 rows x 128B] = 16KB
#define SM_W    16384      // 2 bufs x [256 rows x 128B] = 64KB
#define SM_BW   81920      // float2[512] = 4KB
#define SM_RED  86016      // float[4][64] = 1KB
#define SMEM_TOTAL 87040

__global__ __launch_bounds__(256, 2)
void critic_hmma(const float* __restrict__ b2,
                 const float* __restrict__ W3,
                 const float* __restrict__ b3p,
                 float* __restrict__ out) {
    extern __shared__ char smem[];
    const uint32_t sb = smem_u32(smem);
    const int t = threadIdx.x;
    const int lane = t & 31;
    const int w = t >> 5;
    const int mw = w & 1;        // m-warp: 0..1 (32 rows each)
    const int nw = w >> 1;       // n-warp: 0..3 (64 cols each within stage)
    const int g = lane >> 2;
    const int t4 = lane & 3;
    const int i0 = blockIdx.y * 8;
    const int j0 = blockIdx.x * 8;

    // preload {b2, W3} pairs
    for (int q = t; q < 512; q += 256)
        *(float2*)(smem + SM_BW + q * 8) = make_float2(b2[q], W3[q]);

    // ---- A generator: chunk = 64m x 64k fp16 (8KB), swizzled 128B rows
    auto genA = [&](int kc, int abuf) {
#pragma unroll
        for (int r = 0; r < 2; ++r) {
            int item = t + r * 256;          // 0..511
            int m = item >> 3;               // 0..63
            int c = item & 7;                // 16B column within 128B row
            int kg = kc * 64 + c * 8;
            const float* hxp = &g_hx[(i0 + (m >> 3)) * H + kg];
            const float* hyp = &g_hyb[(j0 + (m & 7)) * H + kg];
            float4 x0 = *(const float4*)hxp, x1 = *(const float4*)(hxp + 4);
            float4 y0 = *(const float4*)hyp, y1 = *(const float4*)(hyp + 4);
            __half2 h0 = __float22half2_rn(make_float2(
                fmaxf(x0.x + y0.x, 0.f), fmaxf(x0.y + y0.y, 0.f)));
            __half2 h1 = __float22half2_rn(make_float2(
                fmaxf(x0.z + y0.z, 0.f), fmaxf(x0.w + y0.w, 0.f)));
            __half2 h2 = __float22half2_rn(make_float2(
                fmaxf(x1.x + y1.x, 0.f), fmaxf(x1.y + y1.y, 0.f)));
            __half2 h3 = __float22half2_rn(make_float2(
                fmaxf(x1.z + y1.z, 0.f), fmaxf(x1.w + y1.w, 0.f)));
            uint32_t off = (uint32_t)(abuf * 8192 + m * 128) +
                           (((uint32_t)(c * 16)) ^ ((uint32_t)((m & 7) << 4)));
            *(uint4*)(smem + SM_A + off) =
                make_uint4(*(uint32_t*)&h0, *(uint32_t*)&h1,
                           *(uint32_t*)&h2, *(uint32_t*)&h3);
        }
    };

    // ---- W producer: stage tile 256n x 64k (32KB), cp.async
    auto produceW = [&](int nt, int kc, int buf) {
#pragma unroll
        for (int r = 0; r < 8; ++r) {
            int item = t + r * 256;          // 0..2047
            int n = item >> 3;               // 0..255 local n
            int c = item & 7;
            const __half* src = &g_W2h[(nt * 256 + n) * H + kc * 64 + c * 8];
            uint32_t off = (uint32_t)(buf * 32768 + n * 128) +
                           (((uint32_t)(c * 16)) ^ ((uint32_t)((n & 7) << 4)));
            cp16(sb + SM_W + off, src);
        }
        asm volatile("cp.async.commit_group;" ::: "memory");
    };

    // ldmatrix A lane mapping (warp covers rows mw*32 .. +32 of 64)
    const int a_row_l = lane & 15;
    const int a_kh = lane >> 4;
    uint32_t a_base[2], a_cs[2];
#pragma unroll
    for (int tm = 0; tm < 2; tm++) {
        int row = mw * 32 + tm * 16 + a_row_l;
        a_base[tm] = sb + SM_A + row * 128;
        a_cs[tm] = (uint32_t)((row & 7) << 4) ^ (uint32_t)(a_kh * 16);
    }
    // ldmatrix B lane mapping (x4 covers 16 n x 16 k); p = 0..3 -> 64 local n
    const int b_n_l = ((lane >> 4) << 3) + (lane & 7);
    const int b_kh = (lane >> 3) & 1;
    uint32_t b_off[4], b_cs[4];
#pragma unroll
    for (int p = 0; p < 4; p++) {
        int n = nw * 64 + p * 16 + b_n_l;    // local n within 256-n stage
        b_off[p] = (uint32_t)(n * 128);
        b_cs[p] = (uint32_t)((n & 7) << 4) ^ (uint32_t)(b_kh * 16);
    }

    float pm[4];
#pragma unroll
    for (int q = 0; q < 4; q++) pm[q] = 0.f;

    float acc[2][8][4];
#pragma unroll
    for (int a = 0; a < 2; a++)
#pragma unroll
        for (int b = 0; b < 8; b++)
#pragma unroll
            for (int c = 0; c < 4; c++) acc[a][b][c] = 0.f;

    // prologue: stage 0 inputs
    produceW(0, 0, 0);
    genA(0, 0);

    for (int s = 0; s < 16; ++s) {
        const int nt = s >> 3, kc = s & 7, buf = s & 1;

        asm volatile("cp.async.wait_group 0;" ::: "memory");
        __syncthreads();   // W(s)+A(s) ready; stage s-1 readers done

        // issue next stage's W into the other buffer (flows under compute)
        if (s + 1 < 16)
            produceW((s + 1) >> 3, (s + 1) & 7, (s + 1) & 1);

        const uint32_t abase = (uint32_t)(buf * 8192);
        const uint32_t wbase = sb + SM_W + (uint32_t)(buf * 32768);
#pragma unroll
        for (int ks = 0; ks < 4; ks++) {
            uint32_t af[2][4];
#pragma unroll
            for (int tm = 0; tm < 2; tm++)
                ldm_x4(af[tm][0], af[tm][1], af[tm][2], af[tm][3],
                       a_base[tm] + abase + ((uint32_t)(ks * 32) ^ a_cs[tm]));
            uint32_t bf[4][4];
#pragma unroll
            for (int p = 0; p < 4; p++)
                ldm_x4(bf[p][0], bf[p][1], bf[p][2], bf[p][3],
                       wbase + b_off[p] + ((uint32_t)(ks * 32) ^ b_cs[p]));
#pragma unroll
            for (int tm = 0; tm < 2; tm++)
#pragma unroll
                for (int tn = 0; tn < 8; tn++)
                    mma16816(acc[tm][tn], af[tm][0], af[tm][1], af[tm][2],
                             af[tm][3], bf[tn >> 1][(tn & 1) * 2],
                             bf[tn >> 1][(tn & 1) * 2 + 1]);
        }

        // regenerate A for next stage into the other buffer (safe: no one
        // reads that buffer until after the next __syncthreads)
        if (s + 1 < 16)
            genA((s + 1) & 7, (s + 1) & 1);

        if (kc == 7) {
            // ---- fold this 256-n half: relu(D + b2) . W3 into pm
#pragma unroll
            for (int tm = 0; tm < 2; tm++)
#pragma unroll
                for (int tn = 0; tn < 8; tn++) {
                    int n_g = nt * 256 + nw * 64 + tn * 8 + 2 * t4;
                    float2 bw0 = *(const float2*)(smem + SM_BW + n_g * 8);
                    float2 bw1 = *(const float2*)(smem + SM_BW + (n_g + 1) * 8);
                    pm[tm * 2] = fmaf(fmaxf(acc[tm][tn][0] + bw0.x, 0.f), bw0.y,
                                      pm[tm * 2]);
                    pm[tm * 2] = fmaf(fmaxf(acc[tm][tn][1] + bw1.x, 0.f), bw1.y,
                                      pm[tm * 2]);
                    pm[tm * 2 + 1] = fmaf(fmaxf(acc[tm][tn][2] + bw0.x, 0.f),
                                          bw0.y, pm[tm * 2 + 1]);
                    pm[tm * 2 + 1] = fmaf(fmaxf(acc[tm][tn][3] + bw1.x, 0.f),
                                          bw1.y, pm[tm * 2 + 1]);
                    acc[tm][tn][0] = 0.f;
                    acc[tm][tn][1] = 0.f;
                    acc[tm][tn][2] = 0.f;
                    acc[tm][tn][3] = 0.f;
                }
        }
    }

    // ---- reduce pm across the 4 lanes of each row group
#pragma unroll
    for (int q = 0; q < 4; q++) {
        pm[q] += __shfl_xor_sync(0xffffffffu, pm[q], 1);
        pm[q] += __shfl_xor_sync(0xffffffffu, pm[q], 2);
    }
    __syncthreads();
    if (t4 == 0) {
        float* red = (float*)(smem + SM_RED);
#pragma unroll
        for (int tm = 0; tm < 2; tm++) {
            red[nw * 64 + mw * 32 + tm * 16 + g] = pm[tm * 2];
            red[nw * 64 + mw * 32 + tm * 16 + 8 + g] = pm[tm * 2 + 1];
        }
    }
    __syncthreads();
    if (t < 64) {
        const float* red = (const float*)(smem + SM_RED);
        float s = red[t] + red[64 + t] + red[128 + t] + red[192 + t] + b3p[0];
        out[(i0 + (t >> 3)) * B + j0 + (t & 7)] = s;
    }
}

// ---------------------------------------------------------------------------
extern "C" void kernel_launch(void* const* d_in, const int* in_sizes, int n_in,
                              void* d_out, int out_size) {
    const float* x  = (const float*)d_in[0];
    const float* y  = (const float*)d_in[1];
    const float* W1 = (const float*)d_in[2];
    const float* b1 = (const float*)d_in[3];
    const float* W2 = (const float*)d_in[4];
    const float* b2 = (const float*)d_in[5];
    const float* W3 = (const float*)d_in[6];
    const float* b3 = (const float*)d_in[7];
    float* out = (float*)d_out;

    cudaFuncSetAttribute(critic_hmma, cudaFuncAttributeMaxDynamicSharedMemorySize,
                         SMEM_TOTAL);

    dim3 gblk(16, 16);
    dim3 ggrd(H / 16, B / 16);
    gemm_h_kernel<<<ggrd, gblk>>>(x, W1, b1, 0, 0);    // -> g_hx
    gemm_h_kernel<<<ggrd, gblk>>>(y, W1, b1, DX, 1);   // -> g_hyb (+b1)
    wconv_kernel<<<H * H / 256, 256>>>(W2);            // -> g_W2h

    critic_hmma<<<dim3(B / 8, B / 8), 256, SMEM_TOTAL>>>(b2, W3, b3, out);
}

// round 15
// speedup vs baseline: 1.2736x; 1.0854x over previous
#include <cuda_runtime.h>
#include <cuda_fp16.h>
#include <cstdint>

#define B 512
#define DX 128
#define H 512

// ---------------- scratch (no allocs allowed) ----------------
__device__ __half g_hx16[B * H];
__device__ __half g_hyb16[B * H];
__device__ __half g_W2h[H * H];

// ---------------------------------------------------------------------------
// Layer 1: out[r][h] = fp16( sum_d in[r][d] * W1[h][off+d] (+ b1[h]) )
// ---------------------------------------------------------------------------
__global__ void gemm_h_kernel(const float* __restrict__ in,
                              const float* __restrict__ W1,
                              const float* __restrict__ b1,
                              int off, int addb) {
    __shared__ float xs[16][17];
    __shared__ float ws[16][17];
    int tx = threadIdx.x, ty = threadIdx.y;
    int r0 = blockIdx.y * 16, h0 = blockIdx.x * 16;
    float acc = 0.f;
    for (int kt = 0; kt < DX; kt += 16) {
        xs[ty][tx] = in[(r0 + ty) * DX + kt + tx];
        ws[ty][tx] = W1[(h0 + ty) * (2 * DX) + off + kt + tx];
        __syncthreads();
#pragma unroll
        for (int k = 0; k < 16; k++)
            acc = fmaf(xs[ty][k], ws[tx][k], acc);
        __syncthreads();
    }
    float bv = addb ? b1[h0 + tx] : 0.f;
    __half* outp = addb ? g_hyb16 : g_hx16;
    outp[(r0 + ty) * H + h0 + tx] = __float2half_rn(acc + bv);
}

// ---------------------------------------------------------------------------
// Convert W2 fp32 -> fp16 (single copy)
// ---------------------------------------------------------------------------
__global__ void wconv_kernel(const float* __restrict__ W2) {
    int idx = blockIdx.x * 256 + threadIdx.x;
    g_W2h[idx] = __float2half_rn(W2[idx]);
}

// ---------------------------------------------------------------------------
// helpers
// ---------------------------------------------------------------------------
__device__ __forceinline__ uint32_t smem_u32(const void* p) {
    uint32_t a;
    asm("{ .reg .u64 t; cvta.to.shared.u64 t, %1; cvt.u32.u64 %0, t; }"
        : "=r"(a) : "l"(p));
    return a;
}
__device__ __forceinline__ void ldm_x4(uint32_t& r0, uint32_t& r1,
                                       uint32_t& r2, uint32_t& r3, uint32_t a) {
    asm volatile("ldmatrix.sync.aligned.m8n8.x4.shared.b16 {%0,%1,%2,%3}, [%4];"
                 : "=r"(r0), "=r"(r1), "=r"(r2), "=r"(r3) : "r"(a));
}
__device__ __forceinline__ void mma16816(float* c, uint32_t a0, uint32_t a1,
                                         uint32_t a2, uint32_t a3,
                                         uint32_t b0, uint32_t b1) {
    asm volatile(
        "mma.sync.aligned.m16n8k16.row.col.f32.f16.f16.f32 "
        "{%0,%1,%2,%3}, {%4,%5,%6,%7}, {%8,%9}, {%0,%1,%2,%3};"
        : "+f"(c[0]), "+f"(c[1]), "+f"(c[2]), "+f"(c[3])
        : "r"(a0), "r"(a1), "r"(a2), "r"(a3), "r"(b0), "r"(b1));
}
__device__ __forceinline__ void cp16(uint32_t dst, const void* src) {
    asm volatile("cp.async.cg.shared.global [%0], [%1], 16;"
                 :: "r"(dst), "l"(src));
}

// ---------------------------------------------------------------------------
// Main fused kernel: fp16 HMMA, 2 CTAs/SM, fp16 A-generation path.
//
// R14 (2 CTAs/SM) cut 445->403us, tensor 50.6->59.2%. Now alu+fma = 26.5%
// is first-order: the per-stage genA regeneration in fp32. This round the
// layer-1 outputs are stored fp16 so genA is pure half2 (2x16B loads + 4
// hadd2 + 4 hmax2 per 16B output): genA load bytes halve, ALU/FMA ~2.5x
// cheaper. Everything else identical to R14.
// ---------------------------------------------------------------------------
#define SM_A    0          // 2 bufs x [64 rows x 128B] = 16KB
#define SM_W    16384      // 2 bufs x [256 rows x 128B] = 64KB
#define SM_BW   81920      // float2[512] = 4KB
#define SM_RED  86016      // float[4][64] = 1KB
#define SMEM_TOTAL 87040

__global__ __launch_bounds__(256, 2)
void critic_hmma(const float* __restrict__ b2,
                 const float* __restrict__ W3,
                 const float* __restrict__ b3p,
                 float* __restrict__ out) {
    extern __shared__ char smem[];
    const uint32_t sb = smem_u32(smem);
    const int t = threadIdx.x;
    const int lane = t & 31;
    const int w = t >> 5;
    const int mw = w & 1;        // m-warp: 0..1 (32 rows each)
    const int nw = w >> 1;       // n-warp: 0..3 (64 cols each within stage)
    const int g = lane >> 2;
    const int t4 = lane & 3;
    const int i0 = blockIdx.y * 8;
    const int j0 = blockIdx.x * 8;

    // preload {b2, W3} pairs
    for (int q = t; q < 512; q += 256)
        *(float2*)(smem + SM_BW + q * 8) = make_float2(b2[q], W3[q]);

    // ---- A generator: chunk = 64m x 64k fp16 (8KB), pure half2 math
    auto genA = [&](int kc, int abuf) {
#pragma unroll
        for (int r = 0; r < 2; ++r) {
            int item = t + r * 256;          // 0..511
            int m = item >> 3;               // 0..63
            int c = item & 7;                // 16B column within 128B row
            int kg = kc * 64 + c * 8;
            uint4 xv = *(const uint4*)&g_hx16[(i0 + (m >> 3)) * H + kg];
            uint4 yv = *(const uint4*)&g_hyb16[(j0 + (m & 7)) * H + kg];
            const __half2 z = __float2half2_rn(0.f);
            __half2 h0 = __hmax2(__hadd2(*(__half2*)&xv.x, *(__half2*)&yv.x), z);
            __half2 h1 = __hmax2(__hadd2(*(__half2*)&xv.y, *(__half2*)&yv.y), z);
            __half2 h2 = __hmax2(__hadd2(*(__half2*)&xv.z, *(__half2*)&yv.z), z);
            __half2 h3 = __hmax2(__hadd2(*(__half2*)&xv.w, *(__half2*)&yv.w), z);
            uint32_t off = (uint32_t)(abuf * 8192 + m * 128) +
                           (((uint32_t)(c * 16)) ^ ((uint32_t)((m & 7) << 4)));
            *(uint4*)(smem + SM_A + off) =
                make_uint4(*(uint32_t*)&h0, *(uint32_t*)&h1,
                           *(uint32_t*)&h2, *(uint32_t*)&h3);
        }
    };

    // ---- W producer: stage tile 256n x 64k (32KB), cp.async
    auto produceW = [&](int nt, int kc, int buf) {
#pragma unroll
        for (int r = 0; r < 8; ++r) {
            int item = t + r * 256;          // 0..2047
            int n = item >> 3;               // 0..255 local n
            int c = item & 7;
            const __half* src = &g_W2h[(nt * 256 + n) * H + kc * 64 + c * 8];
            uint32_t off = (uint32_t)(buf * 32768 + n * 128) +
                           (((uint32_t)(c * 16)) ^ ((uint32_t)((n & 7) << 4)));
            cp16(sb + SM_W + off, src);
        }
        asm volatile("cp.async.commit_group;" ::: "memory");
    };

    // ldmatrix A lane mapping (warp covers rows mw*32 .. +32 of 64)
    const int a_row_l = lane & 15;
    const int a_kh = lane >> 4;
    uint32_t a_base[2], a_cs[2];
#pragma unroll
    for (int tm = 0; tm < 2; tm++) {
        int row = mw * 32 + tm * 16 + a_row_l;
        a_base[tm] = sb + SM_A + row * 128;
        a_cs[tm] = (uint32_t)((row & 7) << 4) ^ (uint32_t)(a_kh * 16);
    }
    // ldmatrix B lane mapping (x4 covers 16 n x 16 k); p = 0..3 -> 64 local n
    const int b_n_l = ((lane >> 4) << 3) + (lane & 7);
    const int b_kh = (lane >> 3) & 1;
    uint32_t b_off[4], b_cs[4];
#pragma unroll
    for (int p = 0; p < 4; p++) {
        int n = nw * 64 + p * 16 + b_n_l;    // local n within 256-n stage
        b_off[p] = (uint32_t)(n * 128);
        b_cs[p] = (uint32_t)((n & 7) << 4) ^ (uint32_t)(b_kh * 16);
    }

    float pm[4];
#pragma unroll
    for (int q = 0; q < 4; q++) pm[q] = 0.f;

    float acc[2][8][4];
#pragma unroll
    for (int a = 0; a < 2; a++)
#pragma unroll
        for (int b = 0; b < 8; b++)
#pragma unroll
            for (int c = 0; c < 4; c++) acc[a][b][c] = 0.f;

    // prologue: stage 0 inputs
    produceW(0, 0, 0);
    genA(0, 0);

    for (int s = 0; s < 16; ++s) {
        const int nt = s >> 3, kc = s & 7, buf = s & 1;

        asm volatile("cp.async.wait_group 0;" ::: "memory");
        __syncthreads();   // W(s)+A(s) ready; stage s-1 readers done

        // issue next stage's W into the other buffer (flows under compute)
        if (s + 1 < 16)
            produceW((s + 1) >> 3, (s + 1) & 7, (s + 1) & 1);

        const uint32_t abase = (uint32_t)(buf * 8192);
        const uint32_t wbase = sb + SM_W + (uint32_t)(buf * 32768);
#pragma unroll
        for (int ks = 0; ks < 4; ks++) {
            uint32_t af[2][4];
#pragma unroll
            for (int tm = 0; tm < 2; tm++)
                ldm_x4(af[tm][0], af[tm][1], af[tm][2], af[tm][3],
                       a_base[tm] + abase + ((uint32_t)(ks * 32) ^ a_cs[tm]));
            uint32_t bf[4][4];
#pragma unroll
            for (int p = 0; p < 4; p++)
                ldm_x4(bf[p][0], bf[p][1], bf[p][2], bf[p][3],
                       wbase + b_off[p] + ((uint32_t)(ks * 32) ^ b_cs[p]));
#pragma unroll
            for (int tm = 0; tm < 2; tm++)
#pragma unroll
                for (int tn = 0; tn < 8; tn++)
                    mma16816(acc[tm][tn], af[tm][0], af[tm][1], af[tm][2],
                             af[tm][3], bf[tn >> 1][(tn & 1) * 2],
                             bf[tn >> 1][(tn & 1) * 2 + 1]);
        }

        // regenerate A for next stage into the other buffer
        if (s + 1 < 16)
            genA((s + 1) & 7, (s + 1) & 1);

        if (kc == 7) {
            // ---- fold this 256-n half: relu(D + b2) . W3 into pm
#pragma unroll
            for (int tm = 0; tm < 2; tm++)
#pragma unroll
                for (int tn = 0; tn < 8; tn++) {
                    int n_g = nt * 256 + nw * 64 + tn * 8 + 2 * t4;
                    float2 bw0 = *(const float2*)(smem + SM_BW + n_g * 8);
                    float2 bw1 = *(const float2*)(smem + SM_BW + (n_g + 1) * 8);
                    pm[tm * 2] = fmaf(fmaxf(acc[tm][tn][0] + bw0.x, 0.f), bw0.y,
                                      pm[tm * 2]);
                    pm[tm * 2] = fmaf(fmaxf(acc[tm][tn][1] + bw1.x, 0.f), bw1.y,
                                      pm[tm * 2]);
                    pm[tm * 2 + 1] = fmaf(fmaxf(acc[tm][tn][2] + bw0.x, 0.f),
                                          bw0.y, pm[tm * 2 + 1]);
                    pm[tm * 2 + 1] = fmaf(fmaxf(acc[tm][tn][3] + bw1.x, 0.f),
                                          bw1.y, pm[tm * 2 + 1]);
                    acc[tm][tn][0] = 0.f;
                    acc[tm][tn][1] = 0.f;
                    acc[tm][tn][2] = 0.f;
                    acc[tm][tn][3] = 0.f;
                }
        }
    }

    // ---- reduce pm across the 4 lanes of each row group
#pragma unroll
    for (int q = 0; q < 4; q++) {
        pm[q] += __shfl_xor_sync(0xffffffffu, pm[q], 1);
        pm[q] += __shfl_xor_sync(0xffffffffu, pm[q], 2);
    }
    __syncthreads();
    if (t4 == 0) {
        float* red = (float*)(smem + SM_RED);
#pragma unroll
        for (int tm = 0; tm < 2; tm++) {
            red[nw * 64 + mw * 32 + tm * 16 + g] = pm[tm * 2];
            red[nw * 64 + mw * 32 + tm * 16 + 8 + g] = pm[tm * 2 + 1];
        }
    }
    __syncthreads();
    if (t < 64) {
        const float* red = (const float*)(smem + SM_RED);
        float s = red[t] + red[64 + t] + red[128 + t] + red[192 + t] + b3p[0];
        out[(i0 + (t >> 3)) * B + j0 + (t & 7)] = s;
    }
}

// ---------------------------------------------------------------------------
extern "C" void kernel_launch(void* const* d_in, const int* in_sizes, int n_in,
                              void* d_out, int out_size) {
    const float* x  = (const float*)d_in[0];
    const float* y  = (const float*)d_in[1];
    const float* W1 = (const float*)d_in[2];
    const float* b1 = (const float*)d_in[3];
    const float* W2 = (const float*)d_in[4];
    const float* b2 = (const float*)d_in[5];
    const float* W3 = (const float*)d_in[6];
    const float* b3 = (const float*)d_in[7];
    float* out = (float*)d_out;

    cudaFuncSetAttribute(critic_hmma, cudaFuncAttributeMaxDynamicSharedMemorySize,
                         SMEM_TOTAL);

    dim3 gblk(16, 16);
    dim3 ggrd(H / 16, B / 16);
    gemm_h_kernel<<<ggrd, gblk>>>(x, W1, b1, 0, 0);    // -> g_hx16
    gemm_h_kernel<<<ggrd, gblk>>>(y, W1, b1, DX, 1);   // -> g_hyb16 (+b1)
    wconv_kernel<<<H * H / 256, 256>>>(W2);            // -> g_W2h

    critic_hmma<<<dim3(B / 8, B / 8), 256, SMEM_TOTAL>>>(b2, W3, b3, out);
}